// round 15
// baseline (speedup 1.0000x reference)
#include <cuda_runtime.h>
#include <cuda_fp16.h>
#include <math.h>
#include <stdint.h>

#define Bc 4
#define Sc 2048
#define Dc 576
#define Hc 9
#define HDc 64
#define FFc 1536
#define Ec 8
#define Tc (Bc*Sc)
#define NKVc (Hc*2*HDc)
#define QKVN (Dc + NKVc)   // 1728

// ---------------- scratch ----------------
static __device__ __align__(16) __half g_xn  [Tc*Dc];
static __device__ __align__(16) __half g_qkv [Tc*QKVN];   // q | kv combined (fp16)
static __device__ __align__(16) __half g_ao  [Tc*Dc];
static __device__ __align__(16) float  g_x2  [Tc*Dc];
static __device__ __align__(16) float  g_xn2 [Tc*Dc];
static __device__ __align__(16) __half g_xn2h[Tc*Dc];
static __device__ __align__(16) __half g_hs  [Tc*FFc];
static __device__ __align__(16) float  g_sh  [Tc*Dc];
static __device__ __align__(16) __half g_hbuf[2*Tc*FFc];
static __device__ __align__(16) float  g_eo  [2*Tc*Dc];
// fp16 transposed weights [N][K]
static __device__ __align__(16) __half g_qkvT[QKVN*Dc];
static __device__ __align__(16) __half g_owT [Dc*Dc];
static __device__ __align__(16) __half g_sw1T[FFc*Dc];
static __device__ __align__(16) __half g_sw3T[FFc*Dc];
static __device__ __align__(16) __half g_sw2T[Dc*FFc];
static __device__ __align__(16) __half g_w1T [Ec*FFc*Dc];
static __device__ __align__(16) __half g_w3T [Ec*FFc*Dc];
static __device__ __align__(16) __half g_w2T [Ec*Dc*FFc];
static __device__ int   g_cnt [Ec];
static __device__ int   g_base[Ec];
static __device__ int   g_list[Ec*Tc];
static __device__ int   g_eidx[2*Tc];
static __device__ int   g_epos[2*Tc];
static __device__ float g_wgt [2*Tc];

__device__ __forceinline__ float geluf(float x){
    return 0.5f*x*(1.0f + erff(x*0.70710678118654752f));
}
__device__ __forceinline__ uint32_t smem_u32(const void* p){
    uint32_t a;
    asm("{ .reg .u64 t; cvta.to.shared.u64 t, %1; cvt.u32.u64 %0, t; }" : "=r"(a) : "l"(p));
    return a;
}
__device__ __forceinline__ void mma_f16(float* c,
    uint32_t a0,uint32_t a1,uint32_t a2,uint32_t a3, uint32_t b0,uint32_t b1){
    asm("mma.sync.aligned.m16n8k16.row.col.f32.f16.f16.f32 "
        "{%0,%1,%2,%3},{%4,%5,%6,%7},{%8,%9},{%0,%1,%2,%3};"
        : "+f"(c[0]),"+f"(c[1]),"+f"(c[2]),"+f"(c[3])
        : "r"(a0),"r"(a1),"r"(a2),"r"(a3),"r"(b0),"r"(b1));
}
__device__ __forceinline__ void ldsm4(uint32_t* r, uint32_t a){
    asm volatile("ldmatrix.sync.aligned.m8n8.x4.shared.b16 {%0,%1,%2,%3}, [%4];"
        : "=r"(r[0]),"=r"(r[1]),"=r"(r[2]),"=r"(r[3]) : "r"(a));
}
__device__ __forceinline__ void cpa16(uint32_t dst, const void* src, bool pred){
    asm volatile("cp.async.cg.shared.global [%0], [%1], 16, %2;"
        :: "r"(dst), "l"(src), "r"(pred ? 16 : 0));
}
#define CP_COMMIT() asm volatile("cp.async.commit_group;" ::: "memory")
#define CP_WAIT1()  asm volatile("cp.async.wait_group 1;" ::: "memory")
#define CP_WAIT2()  asm volatile("cp.async.wait_group 2;" ::: "memory")
#define CP_WAIT0()  asm volatile("cp.async.wait_group 0;" ::: "memory")

// stage sizes (bytes); row pitch 80B (40 halves)
#define PSTG (128*80 + 64*80)      // plain chunk: A + B = 15360
#define DSTG (128*80 + 2*64*80)    // dual chunk: A + B1 + B3 = 20480
#define SM_P (6*PSTG)              // 3 pair-groups x 2 chunks = 92160
#define SM_D (4*DSTG)              // 81920

// ---------------- merged weight transpose: fp32[K][N] -> fp16[N][K] ----------------
struct TranspArgs {
    const float* src[9];
    __half*      dst[9];
    int K[9], N[9];
    int cum[10];
};
__global__ void transp_all(TranspArgs ta){
    __shared__ float tile[32][33];
    int bid = blockIdx.x;
    int e = 0;
    #pragma unroll
    for (int i = 0; i < 9; i++) if (bid >= ta.cum[i+1]) e = i+1;
    int local = bid - ta.cum[e];
    int K = ta.K[e], N = ta.N[e];
    int tilesX = N >> 5, tilesY = K >> 5;
    int perB = tilesX * tilesY;
    int z = local / perB, r = local % perB;
    int n0 = (r % tilesX) << 5, k0 = (r / tilesX) << 5;
    const float* src = ta.src[e] + (size_t)z*K*N;
    __half*      dst = ta.dst[e] + (size_t)z*K*N;
    for (int i = threadIdx.y; i < 32; i += 8)
        tile[i][threadIdx.x] = src[(size_t)(k0+i)*N + n0 + threadIdx.x];
    __syncthreads();
    for (int i = threadIdx.y; i < 32; i += 8)
        dst[(size_t)(n0+i)*K + k0 + threadIdx.x] = __float2half(tile[threadIdx.x][i]);
}

// ---------------- RMSNorm: fp16 out (+ optional fp32 copy) ----------------
__global__ void rms_kernel(const float* __restrict__ x, __half* __restrict__ yh,
                           float* __restrict__ yf){
    int t = blockIdx.x;
    const float* xr = x + (size_t)t*Dc;
    float s = 0.f;
    for (int d = threadIdx.x; d < Dc; d += 256){ float v = xr[d]; s += v*v; }
    #pragma unroll
    for (int o = 16; o; o >>= 1) s += __shfl_xor_sync(0xffffffffu, s, o);
    __shared__ float red[9];
    if ((threadIdx.x & 31) == 0) red[threadIdx.x >> 5] = s;
    __syncthreads();
    if (threadIdx.x == 0){
        float tot = 0.f;
        #pragma unroll
        for (int i = 0; i < 8; i++) tot += red[i];
        red[8] = 1.0f / sqrtf(tot*(1.0f/(float)Dc) + 1e-6f);
    }
    __syncthreads();
    float inv = red[8];
    for (int d = threadIdx.x; d < Dc; d += 256){
        float v = xr[d]*inv;
        yh[(size_t)t*Dc + d] = __float2half(v);
        if (yf) yf[(size_t)t*Dc + d] = v;
    }
}

// ---------------- per-token 9x9 head attention (RoPE fused), fp16 in/out ----------------
__global__ __launch_bounds__(288) void attn_kernel(const __half* __restrict__ qkv,
                                                   __half* __restrict__ ao)
{
    int t = blockIdx.x;
    int h = threadIdx.x >> 5;
    int lane = threadIdx.x & 31;
    int s = t & (Sc-1);
    int b = t >> 11;
    float theta = exp2f(-0.41524101186092029f*(float)lane);
    float fr = (float)s * theta;
    float sn, cs; sincosf(fr, &sn, &cs);
    const __half* row = qkv + (size_t)t*QKVN;
    float2 qv = __half22float2(((const __half2*)(row + h*HDc))[lane]);
    float q0 = qv.x*cs - qv.y*sn;
    float q1 = qv.x*sn + qv.y*cs;
    const __half* kvb = row + Dc;
    float sc[Hc];
    #pragma unroll
    for (int t9 = 0; t9 < Hc; t9++){
        float2 k2 = __half22float2(((const __half2*)(kvb + t9*2*HDc))[lane]);
        float p = q0*k2.x + q1*k2.y;
        #pragma unroll
        for (int o = 16; o; o >>= 1) p += __shfl_xor_sync(0xffffffffu, p, o);
        sc[t9] = p*0.125f;
    }
    float mx = sc[0];
    #pragma unroll
    for (int t9 = 1; t9 < Hc; t9++) mx = fmaxf(mx, sc[t9]);
    float pr[Hc]; float sum = 0.f;
    #pragma unroll
    for (int t9 = 0; t9 < Hc; t9++){ pr[t9] = expf(sc[t9]-mx); sum += pr[t9]; }
    float inv = 1.0f/sum;
    float o0 = 0.f, o1 = 0.f;
    #pragma unroll
    for (int t9 = 0; t9 < Hc; t9++){
        float2 v2 = __half22float2(((const __half2*)(kvb + t9*2*HDc + HDc))[lane]);
        o0 += pr[t9]*v2.x;
        o1 += pr[t9]*v2.y;
    }
    __half2* op = (__half2*)(ao + ((((size_t)(b*Hc + h))*Sc + s)*HDc));
    op[lane] = __floats2half2_rn(o0*inv, o1*inv);
}

// ================= fp16 GEMM: ldmatrix + cp.async, 3 pair-groups (2 chunks/barrier) =================
// Optional fp16 output Ch (if non-null) else fp32 C (+Res).
__global__ __launch_bounds__(256,2) void gemm_f16(const __half* __restrict__ A,
                                                  const __half* __restrict__ BT,
                                                  const float* __restrict__ Res,
                                                  float* __restrict__ C,
                                                  __half* __restrict__ Ch,
                                                  int N, int Kd,
                                                  const int* __restrict__ gather,
                                                  const int* __restrict__ cnts,
                                                  const int* __restrict__ bases,
                                                  long bstride)
{
    extern __shared__ char sm[];
    uint32_t sb = smem_u32(sm);

    int Mloc = Tc; long base = 0; const int* gl = nullptr;
    if (cnts){
        int e = blockIdx.z;
        Mloc = cnts[e]; base = bases[e];
        BT += (size_t)e*bstride;
        if (gather) gl = gather + e*Tc;
    }
    int row0 = blockIdx.y*128;
    if (row0 >= Mloc) return;
    int n0 = blockIdx.x*64;

    const int tid = threadIdx.x, wid = tid>>5, lane = tid&31;
    const int wm = wid & 3, wn = wid >> 2;
    const int g = lane >> 2, tg = lane & 3;

    const int lrow = tid >> 2;
    const int lh8  = (tid & 3) * 8;
    int r0l = row0 + lrow, r1l = row0 + lrow + 64;
    bool v0 = r0l < Mloc, v1 = r1l < Mloc;
    long tok0 = gl ? (v0 ? (long)gl[r0l] : 0) : (base + (v0 ? r0l : 0));
    long tok1 = gl ? (v1 ? (long)gl[r1l] : 0) : (base + (v1 ? r1l : 0));
    const __half* Ap0 = A + (size_t)tok0*Kd + lh8;
    const __half* Ap1 = A + (size_t)tok1*Kd + lh8;
    const __half* Bp  = BT + (size_t)(n0 + lrow)*Kd + lh8;

    uint32_t aDst0 = sb + lrow*80 + lh8*2;
    uint32_t aDst1 = sb + (lrow+64)*80 + lh8*2;
    uint32_t bDst  = sb + 128*80 + lrow*80 + lh8*2;

    const int ra = lane & 15, ca = (lane >> 4) << 3;
    const int rb = (lane & 7) + ((lane >> 4) << 3), cb = lane & 8;
    uint32_t aAdr[2], bAdr[2];
    #pragma unroll
    for (int mt=0; mt<2; mt++) aAdr[mt] = sb + (wm*32 + mt*16 + ra)*80 + ca*2;
    #pragma unroll
    for (int np=0; np<2; np++) bAdr[np] = sb + 128*80 + (wn*32 + np*16 + rb)*80 + cb*2;

    float acc[2][4][4];
    #pragma unroll
    for (int mt=0; mt<2; mt++)
        #pragma unroll
        for (int nt=0; nt<4; nt++)
            #pragma unroll
            for (int i=0;i<4;i++) acc[mt][nt][i]=0.f;

    int nc = Kd >> 5;           // chunks (even)
    int npairs = nc >> 1;

    // prologue: pairs 0,1 into pair-buffers 0,1 (one commit group per pair)
    #pragma unroll 1
    for (int p = 0; p < 2 && p < npairs; p++){
        #pragma unroll
        for (int q = 0; q < 2; q++){
            uint32_t o = (uint32_t)(2*p + q)*PSTG;
            int k0 = (2*p + q) << 5;
            cpa16(aDst0+o, Ap0 + k0, v0);
            cpa16(aDst1+o, Ap1 + k0, v1);
            cpa16(bDst +o, Bp  + k0, true);
        }
        CP_COMMIT();
    }

    for (int p = 0; p < npairs; p++){
        CP_WAIT1();
        __syncthreads();
        int bp = p % 3;
        if (p + 2 < npairs){
            int tp = (p + 2) % 3;
            #pragma unroll
            for (int q = 0; q < 2; q++){
                uint32_t o = (uint32_t)(2*tp + q)*PSTG;
                int k0 = ((p+2)*2 + q) << 5;
                cpa16(aDst0+o, Ap0 + k0, v0);
                cpa16(aDst1+o, Ap1 + k0, v1);
                cpa16(bDst +o, Bp  + k0, true);
            }
        }
        CP_COMMIT();
        #pragma unroll
        for (int q = 0; q < 2; q++){
            uint32_t so = (uint32_t)(2*bp + q)*PSTG;
            #pragma unroll
            for (int h = 0; h < 2; h++){
                uint32_t af[2][4], bf[2][4];
                #pragma unroll
                for (int mt=0; mt<2; mt++) ldsm4(af[mt], aAdr[mt] + so + h*32);
                #pragma unroll
                for (int np=0; np<2; np++) ldsm4(bf[np], bAdr[np] + so + h*32);
                #pragma unroll
                for (int np=0; np<2; np++)
                    #pragma unroll
                    for (int j=0; j<2; j++){
                        int nt = np*2 + j;
                        #pragma unroll
                        for (int mt=0; mt<2; mt++)
                            mma_f16(acc[mt][nt], af[mt][0],af[mt][1],af[mt][2],af[mt][3],
                                    bf[np][j*2], bf[np][j*2+1]);
                    }
            }
        }
    }
    CP_WAIT0();

    #pragma unroll
    for (int mt=0; mt<2; mt++){
        #pragma unroll
        for (int nt=0; nt<4; nt++){
            int r = row0 + wm*32 + mt*16 + g;
            int c = n0 + wn*32 + nt*8 + tg*2;
            if (Ch){
                if (r < Mloc)
                    *(__half2*)&Ch[(size_t)(base+r)*N + c] =
                        __floats2half2_rn(acc[mt][nt][0], acc[mt][nt][1]);
                if (r + 8 < Mloc)
                    *(__half2*)&Ch[(size_t)(base+r+8)*N + c] =
                        __floats2half2_rn(acc[mt][nt][2], acc[mt][nt][3]);
            } else {
                if (r < Mloc){
                    float2 v = make_float2(acc[mt][nt][0], acc[mt][nt][1]);
                    if (Res){
                        const float2 rv = *(const float2*)&Res[(size_t)(base+r)*N + c];
                        v.x += rv.x; v.y += rv.y;
                    }
                    *(float2*)&C[(size_t)(base+r)*N + c] = v;
                }
                if (r + 8 < Mloc){
                    float2 v = make_float2(acc[mt][nt][2], acc[mt][nt][3]);
                    if (Res){
                        const float2 rv = *(const float2*)&Res[(size_t)(base+r+8)*N + c];
                        v.x += rv.x; v.y += rv.y;
                    }
                    *(float2*)&C[(size_t)(base+r+8)*N + c] = v;
                }
            }
        }
    }
}

// ----- dual: C(fp16) = gelu(A@B1T^T)*(A@B3T^T), cp.async 4-stage (R13 config) -----
__global__ __launch_bounds__(256,2) void gemm_dual_f16(const __half* __restrict__ A,
                                                       const __half* __restrict__ B1T,
                                                       const __half* __restrict__ B3T,
                                                       __half* __restrict__ C,
                                                       int N, int Kd,
                                                       const int* __restrict__ gather,
                                                       const int* __restrict__ cnts,
                                                       const int* __restrict__ bases,
                                                       long bstride)
{
    extern __shared__ char sm[];
    uint32_t sb = smem_u32(sm);

    int Mloc = Tc; long base = 0; const int* gl = nullptr;
    if (cnts){
        int e = blockIdx.z;
        Mloc = cnts[e]; base = bases[e];
        B1T += (size_t)e*bstride;
        B3T += (size_t)e*bstride;
        if (gather) gl = gather + e*Tc;
    }
    int row0 = blockIdx.y*128;
    if (row0 >= Mloc) return;
    int n0 = blockIdx.x*64;

    const int tid = threadIdx.x, wid = tid>>5, lane = tid&31;
    const int wm = wid & 3, wn = wid >> 2;
    const int g = lane >> 2, tg = lane & 3;

    const int lrow = tid >> 2;
    const int lh8  = (tid & 3) * 8;
    int r0l = row0 + lrow, r1l = row0 + lrow + 64;
    bool v0 = r0l < Mloc, v1 = r1l < Mloc;
    long tok0 = gl ? (v0 ? (long)gl[r0l] : 0) : (base + (v0 ? r0l : 0));
    long tok1 = gl ? (v1 ? (long)gl[r1l] : 0) : (base + (v1 ? r1l : 0));
    const __half* Ap0 = A + (size_t)tok0*Kd + lh8;
    const __half* Ap1 = A + (size_t)tok1*Kd + lh8;
    const __half* B1p = B1T + (size_t)(n0 + lrow)*Kd + lh8;
    const __half* B3p = B3T + (size_t)(n0 + lrow)*Kd + lh8;

    uint32_t aDst0 = sb + lrow*80 + lh8*2;
    uint32_t aDst1 = sb + (lrow+64)*80 + lh8*2;
    uint32_t b1Dst = sb + 128*80 + lrow*80 + lh8*2;
    uint32_t b3Dst = sb + 128*80 + 64*80 + lrow*80 + lh8*2;

    const int ra = lane & 15, ca = (lane >> 4) << 3;
    const int rb = (lane & 7) + ((lane >> 4) << 3), cb = lane & 8;
    uint32_t aAdr[2], b1Adr[2], b3Adr[2];
    #pragma unroll
    for (int mt=0; mt<2; mt++) aAdr[mt] = sb + (wm*32 + mt*16 + ra)*80 + ca*2;
    #pragma unroll
    for (int np=0; np<2; np++){
        b1Adr[np] = sb + 128*80 + (wn*32 + np*16 + rb)*80 + cb*2;
        b3Adr[np] = sb + 128*80 + 64*80 + (wn*32 + np*16 + rb)*80 + cb*2;
    }

    float acc1[2][4][4], acc3[2][4][4];
    #pragma unroll
    for (int mt=0; mt<2; mt++)
        #pragma unroll
        for (int nt=0; nt<4; nt++)
            #pragma unroll
            for (int i=0;i<4;i++){ acc1[mt][nt][i]=0.f; acc3[mt][nt][i]=0.f; }

    int nc = Kd >> 5;
    #pragma unroll 1
    for (int p = 0; p < 3; p++){
        uint32_t o = p*DSTG; int k0 = p<<5;
        cpa16(aDst0+o, Ap0 + k0, v0);
        cpa16(aDst1+o, Ap1 + k0, v1);
        cpa16(b1Dst+o, B1p + k0, true);
        cpa16(b3Dst+o, B3p + k0, true);
        CP_COMMIT();
    }

    for (int c = 0; c < nc; c++){
        uint32_t so = (uint32_t)(c & 3)*DSTG;
        CP_WAIT2();
        __syncthreads();
        if (c + 3 < nc){
            uint32_t o = (uint32_t)((c+3) & 3)*DSTG; int k0 = (c+3)<<5;
            cpa16(aDst0+o, Ap0 + k0, v0);
            cpa16(aDst1+o, Ap1 + k0, v1);
            cpa16(b1Dst+o, B1p + k0, true);
            cpa16(b3Dst+o, B3p + k0, true);
        }
        CP_COMMIT();
        #pragma unroll
        for (int h = 0; h < 2; h++){
            uint32_t af[2][4], bf1[2][4], bf3[2][4];
            #pragma unroll
            for (int mt=0; mt<2; mt++) ldsm4(af[mt], aAdr[mt] + so + h*32);
            #pragma unroll
            for (int np=0; np<2; np++){
                ldsm4(bf1[np], b1Adr[np] + so + h*32);
                ldsm4(bf3[np], b3Adr[np] + so + h*32);
            }
            #pragma unroll
            for (int np=0; np<2; np++)
                #pragma unroll
                for (int j=0; j<2; j++){
                    int nt = np*2 + j;
                    #pragma unroll
                    for (int mt=0; mt<2; mt++){
                        mma_f16(acc1[mt][nt], af[mt][0],af[mt][1],af[mt][2],af[mt][3],
                                bf1[np][j*2], bf1[np][j*2+1]);
                        mma_f16(acc3[mt][nt], af[mt][0],af[mt][1],af[mt][2],af[mt][3],
                                bf3[np][j*2], bf3[np][j*2+1]);
                    }
                }
        }
    }
    CP_WAIT0();

    #pragma unroll
    for (int mt=0; mt<2; mt++){
        #pragma unroll
        for (int nt=0; nt<4; nt++){
            int r = row0 + wm*32 + mt*16 + g;
            int c = n0 + wn*32 + nt*8 + tg*2;
            if (r < Mloc){
                *(__half2*)&C[(size_t)(base+r)*N + c] = __floats2half2_rn(
                    geluf(acc1[mt][nt][0])*acc3[mt][nt][0],
                    geluf(acc1[mt][nt][1])*acc3[mt][nt][1]);
            }
            if (r + 8 < Mloc){
                *(__half2*)&C[(size_t)(base+r+8)*N + c] = __floats2half2_rn(
                    geluf(acc1[mt][nt][2])*acc3[mt][nt][2],
                    geluf(acc1[mt][nt][3])*acc3[mt][nt][3]);
            }
        }
    }
}

// ---------------- gate + top-2 ----------------
__global__ void zero_cnt_kernel(int* cnt){ if (threadIdx.x < Ec) cnt[threadIdx.x] = 0; }

__global__ void gate_kernel(const float* __restrict__ xn2,
                            const float* __restrict__ gw,
                            int* __restrict__ cnt, int* __restrict__ list,
                            int* __restrict__ eidx, int* __restrict__ epos,
                            float* __restrict__ wgt)
{
    int warp = threadIdx.x >> 5;
    int lane = threadIdx.x & 31;
    int t = blockIdx.x*4 + warp;
    float acc[Ec];
    #pragma unroll
    for (int e = 0; e < Ec; e++) acc[e] = 0.f;
    const float* xr = xn2 + (size_t)t*Dc;
    for (int k = lane; k < Dc; k += 32){
        float xv = xr[k];
        #pragma unroll
        for (int e = 0; e < Ec; e++) acc[e] += xv * gw[k*Ec + e];
    }
    #pragma unroll
    for (int e = 0; e < Ec; e++){
        #pragma unroll
        for (int o = 16; o; o >>= 1) acc[e] += __shfl_xor_sync(0xffffffffu, acc[e], o);
    }
    if (lane == 0){
        float mx = acc[0];
        #pragma unroll
        for (int e = 1; e < Ec; e++) mx = fmaxf(mx, acc[e]);
        float p[Ec];
        #pragma unroll
        for (int e = 0; e < Ec; e++) p[e] = expf(acc[e] - mx);
        int i0 = 0;
        #pragma unroll
        for (int e = 1; e < Ec; e++) if (p[e] > p[i0]) i0 = e;
        int i1 = (i0 == 0) ? 1 : 0;
        #pragma unroll
        for (int e = 0; e < Ec; e++) if (e != i0 && p[e] > p[i1]) i1 = e;
        float tot = p[i0] + p[i1];
        float w0 = p[i0]/tot, w1 = p[i1]/tot;
        int pos0 = atomicAdd(&cnt[i0], 1);
        int pos1 = atomicAdd(&cnt[i1], 1);
        list[i0*Tc + pos0] = t;
        list[i1*Tc + pos1] = t;
        eidx[2*t]   = i0; epos[2*t]   = pos0; wgt[2*t]   = w0;
        eidx[2*t+1] = i1; epos[2*t+1] = pos1; wgt[2*t+1] = w1;
    }
}

__global__ void prefix_kernel(const int* __restrict__ cnt, int* __restrict__ base){
    if (threadIdx.x == 0){
        int a = 0;
        #pragma unroll
        for (int e = 0; e < Ec; e++){ base[e] = a; a += cnt[e]; }
    }
}

// ---------------- final combine ----------------
__global__ void combine_kernel(const float* __restrict__ x2, const float* __restrict__ sh,
                               const float* __restrict__ eo, const int* __restrict__ eidx,
                               const int* __restrict__ epos, const int* __restrict__ bases,
                               const float* __restrict__ wgt, float* __restrict__ out)
{
    int t = blockIdx.x;
    int g0 = bases[eidx[2*t]]   + epos[2*t];
    int g1 = bases[eidx[2*t+1]] + epos[2*t+1];
    float w0 = wgt[2*t], w1 = wgt[2*t+1];
    int d = threadIdx.x*4;
    size_t o = (size_t)t*Dc + d;
    float4 a  = *(const float4*)&x2[o];
    float4 b  = *(const float4*)&sh[o];
    float4 c0 = *(const float4*)&eo[(size_t)g0*Dc + d];
    float4 c1 = *(const float4*)&eo[(size_t)g1*Dc + d];
    float4 r;
    r.x = a.x + b.x + w0*c0.x + w1*c1.x;
    r.y = a.y + b.y + w0*c0.y + w1*c1.y;
    r.z = a.z + b.z + w0*c0.z + w1*c1.z;
    r.w = a.w + b.w + w0*c0.w + w1*c1.w;
    *(float4*)&out[o] = r;
}

// ---------------- launch ----------------
extern "C" void kernel_launch(void* const* d_in, const int* in_sizes, int n_in,
                              void* d_out, int out_size)
{
    const float* x   = (const float*)d_in[0];
    const float* qw  = (const float*)d_in[1];
    const float* kvw = (const float*)d_in[2];
    const float* ow  = (const float*)d_in[3];
    const float* gw  = (const float*)d_in[4];
    const float* w1  = (const float*)d_in[5];
    const float* w2  = (const float*)d_in[6];
    const float* w3  = (const float*)d_in[7];
    const float* sw1 = (const float*)d_in[8];
    const float* sw2 = (const float*)d_in[9];
    const float* sw3 = (const float*)d_in[10];
    float* out = (float*)d_out;

    float *x2,*xn2,*sh,*eo,*wgt;
    __half *xn,*qkv,*ao,*xn2h,*hs,*hbuf;
    __half *qkvT,*owT,*sw1T,*sw3T,*sw2T,*w1T,*w3T,*w2T;
    int *cnt,*base,*list,*eidx,*epos;
    cudaGetSymbolAddress((void**)&xn,   g_xn);
    cudaGetSymbolAddress((void**)&qkv,  g_qkv);
    cudaGetSymbolAddress((void**)&ao,   g_ao);
    cudaGetSymbolAddress((void**)&x2,   g_x2);
    cudaGetSymbolAddress((void**)&xn2,  g_xn2);
    cudaGetSymbolAddress((void**)&xn2h, g_xn2h);
    cudaGetSymbolAddress((void**)&hs,   g_hs);
    cudaGetSymbolAddress((void**)&sh,   g_sh);
    cudaGetSymbolAddress((void**)&hbuf, g_hbuf);
    cudaGetSymbolAddress((void**)&eo,   g_eo);
    cudaGetSymbolAddress((void**)&wgt,  g_wgt);
    cudaGetSymbolAddress((void**)&qkvT, g_qkvT);
    cudaGetSymbolAddress((void**)&owT,  g_owT);
    cudaGetSymbolAddress((void**)&sw1T, g_sw1T);
    cudaGetSymbolAddress((void**)&sw3T, g_sw3T);
    cudaGetSymbolAddress((void**)&sw2T, g_sw2T);
    cudaGetSymbolAddress((void**)&w1T,  g_w1T);
    cudaGetSymbolAddress((void**)&w3T,  g_w3T);
    cudaGetSymbolAddress((void**)&w2T,  g_w2T);
    cudaGetSymbolAddress((void**)&cnt,  g_cnt);
    cudaGetSymbolAddress((void**)&base, g_base);
    cudaGetSymbolAddress((void**)&list, g_list);
    cudaGetSymbolAddress((void**)&eidx, g_eidx);
    cudaGetSymbolAddress((void**)&epos, g_epos);

    cudaFuncSetAttribute(gemm_f16, cudaFuncAttributeMaxDynamicSharedMemorySize, SM_P);
    cudaFuncSetAttribute(gemm_dual_f16, cudaFuncAttributeMaxDynamicSharedMemorySize, SM_D);

    TranspArgs ta;
    const float* srcs[9] = {qw, kvw, ow, sw1, sw3, sw2, w1, w3, w2};
    __half* dsts[9] = {qkvT, qkvT + (size_t)Dc*Dc, owT, sw1T, sw3T, sw2T, w1T, w3T, w2T};
    int Ks[9] = {Dc, Dc, Dc, Dc, Dc, FFc, Dc, Dc, FFc};
    int Ns[9] = {Dc, NKVc, Dc, FFc, FFc, Dc, FFc, FFc, Dc};
    int Bs_[9] = {1, 1, 1, 1, 1, 1, Ec, Ec, Ec};
    int cum = 0;
    for (int i = 0; i < 9; i++){
        ta.src[i] = srcs[i]; ta.dst[i] = dsts[i];
        ta.K[i] = Ks[i]; ta.N[i] = Ns[i];
        ta.cum[i] = cum;
        cum += (Ks[i]/32)*(Ns[i]/32)*Bs_[i];
    }
    ta.cum[9] = cum;
    transp_all<<<cum, dim3(32,8)>>>(ta);

    rms_kernel<<<Tc, 256>>>(x, xn, nullptr);
    // merged q|kv projection (fp16 out)
    gemm_f16<<<dim3(QKVN/64, Tc/128, 1), 256, SM_P>>>(xn, qkvT, nullptr, nullptr, qkv,
                                                      QKVN, Dc, nullptr, nullptr, nullptr, 0);
    attn_kernel<<<Tc, 288>>>(qkv, ao);
    gemm_f16<<<dim3(Dc/64, Tc/128, 1), 256, SM_P>>>(ao, owT, x, x2, nullptr, Dc, Dc,
                                                    nullptr, nullptr, nullptr, 0);
    rms_kernel<<<Tc, 256>>>(x2, xn2h, xn2);
    zero_cnt_kernel<<<1, 32>>>(cnt);
    gate_kernel<<<Tc/4, 128>>>(xn2, gw, cnt, list, eidx, epos, wgt);
    prefix_kernel<<<1, 32>>>(cnt, base);
    // shared expert
    gemm_dual_f16<<<dim3(FFc/64, Tc/128, 1), 256, SM_D>>>(xn2h, sw1T, sw3T, hs, FFc, Dc,
                                                          nullptr, nullptr, nullptr, 0);
    gemm_f16<<<dim3(Dc/64, Tc/128, 1), 256, SM_P>>>(hs, sw2T, nullptr, sh, nullptr, Dc, FFc,
                                                    nullptr, nullptr, nullptr, 0);
    // MoE experts (sparse, gathered)
    gemm_dual_f16<<<dim3(FFc/64, Tc/128, Ec), 256, SM_D>>>(xn2h, w1T, w3T, hbuf, FFc, Dc,
                                                           list, cnt, base, (long)FFc*Dc);
    gemm_f16<<<dim3(Dc/64, Tc/128, Ec), 256, SM_P>>>(hbuf, w2T, nullptr, eo, nullptr, Dc, FFc,
                                                     nullptr, cnt, base, (long)Dc*FFc);
    combine_kernel<<<Tc, 144>>>(x2, sh, eo, eidx, epos, base, wgt, out);
}

// round 16
// speedup vs baseline: 1.0438x; 1.0438x over previous
#include <cuda_runtime.h>
#include <cuda_fp16.h>
#include <math.h>
#include <stdint.h>

#define Bc 4
#define Sc 2048
#define Dc 576
#define Hc 9
#define HDc 64
#define FFc 1536
#define Ec 8
#define NE (Ec+1)          // 8 routed + 1 shared
#define Tc (Bc*Sc)
#define NKVc (Hc*2*HDc)
#define QKVN (Dc + NKVc)   // 1728

// ---------------- scratch ----------------
static __device__ __align__(16) __half g_xn  [Tc*Dc];
static __device__ __align__(16) __half g_qkv [Tc*QKVN];
static __device__ __align__(16) __half g_ao  [Tc*Dc];
static __device__ __align__(16) float  g_x2  [Tc*Dc];
static __device__ __align__(16) float  g_xn2 [Tc*Dc];
static __device__ __align__(16) __half g_xn2h[Tc*Dc];
static __device__ __align__(16) __half g_hbuf[3*Tc*FFc];
static __device__ __align__(16) float  g_eo  [3*Tc*Dc];
// fp16 transposed weights [N][K]; expert slot 8 = shared expert
static __device__ __align__(16) __half g_qkvT[QKVN*Dc];
static __device__ __align__(16) __half g_owT [Dc*Dc];
static __device__ __align__(16) __half g_w1T [NE*FFc*Dc];
static __device__ __align__(16) __half g_w3T [NE*FFc*Dc];
static __device__ __align__(16) __half g_w2T [NE*Dc*FFc];
static __device__ int   g_cnt [NE];
static __device__ int   g_base[NE];
static __device__ int   g_list[NE*Tc];
static __device__ int   g_eidx[2*Tc];
static __device__ int   g_epos[2*Tc];
static __device__ float g_wgt [2*Tc];

__device__ __forceinline__ float geluf(float x){
    return 0.5f*x*(1.0f + erff(x*0.70710678118654752f));
}
__device__ __forceinline__ uint32_t smem_u32(const void* p){
    uint32_t a;
    asm("{ .reg .u64 t; cvta.to.shared.u64 t, %1; cvt.u32.u64 %0, t; }" : "=r"(a) : "l"(p));
    return a;
}
__device__ __forceinline__ void mma_f16(float* c,
    uint32_t a0,uint32_t a1,uint32_t a2,uint32_t a3, uint32_t b0,uint32_t b1){
    asm("mma.sync.aligned.m16n8k16.row.col.f32.f16.f16.f32 "
        "{%0,%1,%2,%3},{%4,%5,%6,%7},{%8,%9},{%0,%1,%2,%3};"
        : "+f"(c[0]),"+f"(c[1]),"+f"(c[2]),"+f"(c[3])
        : "r"(a0),"r"(a1),"r"(a2),"r"(a3),"r"(b0),"r"(b1));
}
__device__ __forceinline__ void ldsm4(uint32_t* r, uint32_t a){
    asm volatile("ldmatrix.sync.aligned.m8n8.x4.shared.b16 {%0,%1,%2,%3}, [%4];"
        : "=r"(r[0]),"=r"(r[1]),"=r"(r[2]),"=r"(r[3]) : "r"(a));
}
__device__ __forceinline__ void cpa16(uint32_t dst, const void* src, bool pred){
    asm volatile("cp.async.cg.shared.global [%0], [%1], 16, %2;"
        :: "r"(dst), "l"(src), "r"(pred ? 16 : 0));
}
#define CP_COMMIT() asm volatile("cp.async.commit_group;" ::: "memory")
#define CP_WAIT2()  asm volatile("cp.async.wait_group 2;" ::: "memory")
#define CP_WAIT0()  asm volatile("cp.async.wait_group 0;" ::: "memory")

#define PSTG (128*80 + 64*80)
#define DSTG (128*80 + 2*64*80)
#define SM_P (4*PSTG)
#define SM_D (4*DSTG)

// ---------------- merged weight transpose: fp32[K][N] -> fp16[N][K] ----------------
struct TranspArgs {
    const float* src[9];
    __half*      dst[9];
    int K[9], N[9];
    int cum[10];
};
__global__ void transp_all(TranspArgs ta){
    __shared__ float tile[32][33];
    int bid = blockIdx.x;
    int e = 0;
    #pragma unroll
    for (int i = 0; i < 9; i++) if (bid >= ta.cum[i+1]) e = i+1;
    int local = bid - ta.cum[e];
    int K = ta.K[e], N = ta.N[e];
    int tilesX = N >> 5, tilesY = K >> 5;
    int perB = tilesX * tilesY;
    int z = local / perB, r = local % perB;
    int n0 = (r % tilesX) << 5, k0 = (r / tilesX) << 5;
    const float* src = ta.src[e] + (size_t)z*K*N;
    __half*      dst = ta.dst[e] + (size_t)z*K*N;
    for (int i = threadIdx.y; i < 32; i += 8)
        tile[i][threadIdx.x] = src[(size_t)(k0+i)*N + n0 + threadIdx.x];
    __syncthreads();
    for (int i = threadIdx.y; i < 32; i += 8)
        dst[(size_t)(n0+i)*K + k0 + threadIdx.x] = __float2half(tile[threadIdx.x][i]);
}

// ---------------- RMSNorm: fp16 out (+ optional fp32 copy) ----------------
__global__ void rms_kernel(const float* __restrict__ x, __half* __restrict__ yh,
                           float* __restrict__ yf){
    int t = blockIdx.x;
    const float* xr = x + (size_t)t*Dc;
    float s = 0.f;
    for (int d = threadIdx.x; d < Dc; d += 256){ float v = xr[d]; s += v*v; }
    #pragma unroll
    for (int o = 16; o; o >>= 1) s += __shfl_xor_sync(0xffffffffu, s, o);
    __shared__ float red[9];
    if ((threadIdx.x & 31) == 0) red[threadIdx.x >> 5] = s;
    __syncthreads();
    if (threadIdx.x == 0){
        float tot = 0.f;
        #pragma unroll
        for (int i = 0; i < 8; i++) tot += red[i];
        red[8] = 1.0f / sqrtf(tot*(1.0f/(float)Dc) + 1e-6f);
    }
    __syncthreads();
    float inv = red[8];
    for (int d = threadIdx.x; d < Dc; d += 256){
        float v = xr[d]*inv;
        yh[(size_t)t*Dc + d] = __float2half(v);
        if (yf) yf[(size_t)t*Dc + d] = v;
    }
}

// ---------------- per-token 9x9 head attention (RoPE fused), fp16 in/out ----------------
__global__ __launch_bounds__(288) void attn_kernel(const __half* __restrict__ qkv,
                                                   __half* __restrict__ ao)
{
    int t = blockIdx.x;
    int h = threadIdx.x >> 5;
    int lane = threadIdx.x & 31;
    int s = t & (Sc-1);
    int b = t >> 11;
    float theta = exp2f(-0.41524101186092029f*(float)lane);
    float fr = (float)s * theta;
    float sn, cs; sincosf(fr, &sn, &cs);
    const __half* row = qkv + (size_t)t*QKVN;
    float2 qv = __half22float2(((const __half2*)(row + h*HDc))[lane]);
    float q0 = qv.x*cs - qv.y*sn;
    float q1 = qv.x*sn + qv.y*cs;
    const __half* kvb = row + Dc;
    float sc[Hc];
    #pragma unroll
    for (int t9 = 0; t9 < Hc; t9++){
        float2 k2 = __half22float2(((const __half2*)(kvb + t9*2*HDc))[lane]);
        float p = q0*k2.x + q1*k2.y;
        #pragma unroll
        for (int o = 16; o; o >>= 1) p += __shfl_xor_sync(0xffffffffu, p, o);
        sc[t9] = p*0.125f;
    }
    float mx = sc[0];
    #pragma unroll
    for (int t9 = 1; t9 < Hc; t9++) mx = fmaxf(mx, sc[t9]);
    float pr[Hc]; float sum = 0.f;
    #pragma unroll
    for (int t9 = 0; t9 < Hc; t9++){ pr[t9] = expf(sc[t9]-mx); sum += pr[t9]; }
    float inv = 1.0f/sum;
    float o0 = 0.f, o1 = 0.f;
    #pragma unroll
    for (int t9 = 0; t9 < Hc; t9++){
        float2 v2 = __half22float2(((const __half2*)(kvb + t9*2*HDc + HDc))[lane]);
        o0 += pr[t9]*v2.x;
        o1 += pr[t9]*v2.y;
    }
    __half2* op = (__half2*)(ao + ((((size_t)(b*Hc + h))*Sc + s)*HDc));
    op[lane] = __floats2half2_rn(o0*inv, o1*inv);
}

// ================= fp16 GEMM: ldmatrix + cp.async 4-stage (R13 config) =================
__global__ __launch_bounds__(256,2) void gemm_f16(const __half* __restrict__ A,
                                                  const __half* __restrict__ BT,
                                                  const float* __restrict__ Res,
                                                  float* __restrict__ C,
                                                  __half* __restrict__ Ch,
                                                  int N, int Kd,
                                                  const int* __restrict__ gather,
                                                  const int* __restrict__ cnts,
                                                  const int* __restrict__ bases,
                                                  long bstride)
{
    extern __shared__ char sm[];
    uint32_t sb = smem_u32(sm);

    int Mloc = Tc; long base = 0; const int* gl = nullptr;
    if (cnts){
        int e = blockIdx.z;
        Mloc = cnts[e]; base = bases[e];
        BT += (size_t)e*bstride;
        if (gather) gl = gather + e*Tc;
    }
    int row0 = blockIdx.y*128;
    if (row0 >= Mloc) return;
    int n0 = blockIdx.x*64;

    const int tid = threadIdx.x, wid = tid>>5, lane = tid&31;
    const int wm = wid & 3, wn = wid >> 2;
    const int g = lane >> 2, tg = lane & 3;

    const int lrow = tid >> 2;
    const int lh8  = (tid & 3) * 8;
    int r0l = row0 + lrow, r1l = row0 + lrow + 64;
    bool v0 = r0l < Mloc, v1 = r1l < Mloc;
    long tok0 = gl ? (v0 ? (long)gl[r0l] : 0) : (base + (v0 ? r0l : 0));
    long tok1 = gl ? (v1 ? (long)gl[r1l] : 0) : (base + (v1 ? r1l : 0));
    const __half* Ap0 = A + (size_t)tok0*Kd + lh8;
    const __half* Ap1 = A + (size_t)tok1*Kd + lh8;
    const __half* Bp  = BT + (size_t)(n0 + lrow)*Kd + lh8;

    uint32_t aDst0 = sb + lrow*80 + lh8*2;
    uint32_t aDst1 = sb + (lrow+64)*80 + lh8*2;
    uint32_t bDst  = sb + 128*80 + lrow*80 + lh8*2;

    const int ra = lane & 15, ca = (lane >> 4) << 3;
    const int rb = (lane & 7) + ((lane >> 4) << 3), cb = lane & 8;
    uint32_t aAdr[2], bAdr[2];
    #pragma unroll
    for (int mt=0; mt<2; mt++) aAdr[mt] = sb + (wm*32 + mt*16 + ra)*80 + ca*2;
    #pragma unroll
    for (int np=0; np<2; np++) bAdr[np] = sb + 128*80 + (wn*32 + np*16 + rb)*80 + cb*2;

    float acc[2][4][4];
    #pragma unroll
    for (int mt=0; mt<2; mt++)
        #pragma unroll
        for (int nt=0; nt<4; nt++)
            #pragma unroll
            for (int i=0;i<4;i++) acc[mt][nt][i]=0.f;

    int nc = Kd >> 5;
    #pragma unroll 1
    for (int p = 0; p < 3; p++){
        uint32_t o = p*PSTG; int k0 = p<<5;
        cpa16(aDst0+o, Ap0 + k0, v0);
        cpa16(aDst1+o, Ap1 + k0, v1);
        cpa16(bDst +o, Bp  + k0, true);
        CP_COMMIT();
    }

    for (int c = 0; c < nc; c++){
        uint32_t so = (uint32_t)(c & 3)*PSTG;
        CP_WAIT2();
        __syncthreads();
        if (c + 3 < nc){
            uint32_t o = (uint32_t)((c+3) & 3)*PSTG; int k0 = (c+3)<<5;
            cpa16(aDst0+o, Ap0 + k0, v0);
            cpa16(aDst1+o, Ap1 + k0, v1);
            cpa16(bDst +o, Bp  + k0, true);
        }
        CP_COMMIT();
        #pragma unroll
        for (int h = 0; h < 2; h++){
            uint32_t af[2][4], bf[2][4];
            #pragma unroll
            for (int mt=0; mt<2; mt++) ldsm4(af[mt], aAdr[mt] + so + h*32);
            #pragma unroll
            for (int np=0; np<2; np++) ldsm4(bf[np], bAdr[np] + so + h*32);
            #pragma unroll
            for (int np=0; np<2; np++)
                #pragma unroll
                for (int j=0; j<2; j++){
                    int nt = np*2 + j;
                    #pragma unroll
                    for (int mt=0; mt<2; mt++)
                        mma_f16(acc[mt][nt], af[mt][0],af[mt][1],af[mt][2],af[mt][3],
                                bf[np][j*2], bf[np][j*2+1]);
                }
        }
    }
    CP_WAIT0();

    #pragma unroll
    for (int mt=0; mt<2; mt++){
        #pragma unroll
        for (int nt=0; nt<4; nt++){
            int r = row0 + wm*32 + mt*16 + g;
            int c = n0 + wn*32 + nt*8 + tg*2;
            if (Ch){
                if (r < Mloc)
                    *(__half2*)&Ch[(size_t)(base+r)*N + c] =
                        __floats2half2_rn(acc[mt][nt][0], acc[mt][nt][1]);
                if (r + 8 < Mloc)
                    *(__half2*)&Ch[(size_t)(base+r+8)*N + c] =
                        __floats2half2_rn(acc[mt][nt][2], acc[mt][nt][3]);
            } else {
                if (r < Mloc){
                    float2 v = make_float2(acc[mt][nt][0], acc[mt][nt][1]);
                    if (Res){
                        const float2 rv = *(const float2*)&Res[(size_t)(base+r)*N + c];
                        v.x += rv.x; v.y += rv.y;
                    }
                    *(float2*)&C[(size_t)(base+r)*N + c] = v;
                }
                if (r + 8 < Mloc){
                    float2 v = make_float2(acc[mt][nt][2], acc[mt][nt][3]);
                    if (Res){
                        const float2 rv = *(const float2*)&Res[(size_t)(base+r+8)*N + c];
                        v.x += rv.x; v.y += rv.y;
                    }
                    *(float2*)&C[(size_t)(base+r+8)*N + c] = v;
                }
            }
        }
    }
}

// ----- dual: C(fp16) = gelu(A@B1T^T)*(A@B3T^T), cp.async 4-stage (R13 config) -----
__global__ __launch_bounds__(256,2) void gemm_dual_f16(const __half* __restrict__ A,
                                                       const __half* __restrict__ B1T,
                                                       const __half* __restrict__ B3T,
                                                       __half* __restrict__ C,
                                                       int N, int Kd,
                                                       const int* __restrict__ gather,
                                                       const int* __restrict__ cnts,
                                                       const int* __restrict__ bases,
                                                       long bstride)
{
    extern __shared__ char sm[];
    uint32_t sb = smem_u32(sm);

    int Mloc = Tc; long base = 0; const int* gl = nullptr;
    if (cnts){
        int e = blockIdx.z;
        Mloc = cnts[e]; base = bases[e];
        B1T += (size_t)e*bstride;
        B3T += (size_t)e*bstride;
        if (gather) gl = gather + e*Tc;
    }
    int row0 = blockIdx.y*128;
    if (row0 >= Mloc) return;
    int n0 = blockIdx.x*64;

    const int tid = threadIdx.x, wid = tid>>5, lane = tid&31;
    const int wm = wid & 3, wn = wid >> 2;
    const int g = lane >> 2, tg = lane & 3;

    const int lrow = tid >> 2;
    const int lh8  = (tid & 3) * 8;
    int r0l = row0 + lrow, r1l = row0 + lrow + 64;
    bool v0 = r0l < Mloc, v1 = r1l < Mloc;
    long tok0 = gl ? (v0 ? (long)gl[r0l] : 0) : (base + (v0 ? r0l : 0));
    long tok1 = gl ? (v1 ? (long)gl[r1l] : 0) : (base + (v1 ? r1l : 0));
    const __half* Ap0 = A + (size_t)tok0*Kd + lh8;
    const __half* Ap1 = A + (size_t)tok1*Kd + lh8;
    const __half* B1p = B1T + (size_t)(n0 + lrow)*Kd + lh8;
    const __half* B3p = B3T + (size_t)(n0 + lrow)*Kd + lh8;

    uint32_t aDst0 = sb + lrow*80 + lh8*2;
    uint32_t aDst1 = sb + (lrow+64)*80 + lh8*2;
    uint32_t b1Dst = sb + 128*80 + lrow*80 + lh8*2;
    uint32_t b3Dst = sb + 128*80 + 64*80 + lrow*80 + lh8*2;

    const int ra = lane & 15, ca = (lane >> 4) << 3;
    const int rb = (lane & 7) + ((lane >> 4) << 3), cb = lane & 8;
    uint32_t aAdr[2], b1Adr[2], b3Adr[2];
    #pragma unroll
    for (int mt=0; mt<2; mt++) aAdr[mt] = sb + (wm*32 + mt*16 + ra)*80 + ca*2;
    #pragma unroll
    for (int np=0; np<2; np++){
        b1Adr[np] = sb + 128*80 + (wn*32 + np*16 + rb)*80 + cb*2;
        b3Adr[np] = sb + 128*80 + 64*80 + (wn*32 + np*16 + rb)*80 + cb*2;
    }

    float acc1[2][4][4], acc3[2][4][4];
    #pragma unroll
    for (int mt=0; mt<2; mt++)
        #pragma unroll
        for (int nt=0; nt<4; nt++)
            #pragma unroll
            for (int i=0;i<4;i++){ acc1[mt][nt][i]=0.f; acc3[mt][nt][i]=0.f; }

    int nc = Kd >> 5;
    #pragma unroll 1
    for (int p = 0; p < 3; p++){
        uint32_t o = p*DSTG; int k0 = p<<5;
        cpa16(aDst0+o, Ap0 + k0, v0);
        cpa16(aDst1+o, Ap1 + k0, v1);
        cpa16(b1Dst+o, B1p + k0, true);
        cpa16(b3Dst+o, B3p + k0, true);
        CP_COMMIT();
    }

    for (int c = 0; c < nc; c++){
        uint32_t so = (uint32_t)(c & 3)*DSTG;
        CP_WAIT2();
        __syncthreads();
        if (c + 3 < nc){
            uint32_t o = (uint32_t)((c+3) & 3)*DSTG; int k0 = (c+3)<<5;
            cpa16(aDst0+o, Ap0 + k0, v0);
            cpa16(aDst1+o, Ap1 + k0, v1);
            cpa16(b1Dst+o, B1p + k0, true);
            cpa16(b3Dst+o, B3p + k0, true);
        }
        CP_COMMIT();
        #pragma unroll
        for (int h = 0; h < 2; h++){
            uint32_t af[2][4], bf1[2][4], bf3[2][4];
            #pragma unroll
            for (int mt=0; mt<2; mt++) ldsm4(af[mt], aAdr[mt] + so + h*32);
            #pragma unroll
            for (int np=0; np<2; np++){
                ldsm4(bf1[np], b1Adr[np] + so + h*32);
                ldsm4(bf3[np], b3Adr[np] + so + h*32);
            }
            #pragma unroll
            for (int np=0; np<2; np++)
                #pragma unroll
                for (int j=0; j<2; j++){
                    int nt = np*2 + j;
                    #pragma unroll
                    for (int mt=0; mt<2; mt++){
                        mma_f16(acc1[mt][nt], af[mt][0],af[mt][1],af[mt][2],af[mt][3],
                                bf1[np][j*2], bf1[np][j*2+1]);
                        mma_f16(acc3[mt][nt], af[mt][0],af[mt][1],af[mt][2],af[mt][3],
                                bf3[np][j*2], bf3[np][j*2+1]);
                    }
                }
        }
    }
    CP_WAIT0();

    #pragma unroll
    for (int mt=0; mt<2; mt++){
        #pragma unroll
        for (int nt=0; nt<4; nt++){
            int r = row0 + wm*32 + mt*16 + g;
            int c = n0 + wn*32 + nt*8 + tg*2;
            if (r < Mloc){
                *(__half2*)&C[(size_t)(base+r)*N + c] = __floats2half2_rn(
                    geluf(acc1[mt][nt][0])*acc3[mt][nt][0],
                    geluf(acc1[mt][nt][1])*acc3[mt][nt][1]);
            }
            if (r + 8 < Mloc){
                *(__half2*)&C[(size_t)(base+r+8)*N + c] = __floats2half2_rn(
                    geluf(acc1[mt][nt][2])*acc3[mt][nt][2],
                    geluf(acc1[mt][nt][3])*acc3[mt][nt][3]);
            }
        }
    }
}

// ---------------- gate + top-2 ----------------
__global__ void init_cnt_kernel(int* cnt){
    if (threadIdx.x < Ec) cnt[threadIdx.x] = 0;
    if (threadIdx.x == Ec) cnt[Ec] = Tc;
}
__global__ void idlist_kernel(int* __restrict__ list){
    int i = blockIdx.x*256 + threadIdx.x;
    list[Ec*Tc + i] = i;
}

__global__ void gate_kernel(const float* __restrict__ xn2,
                            const float* __restrict__ gw,
                            int* __restrict__ cnt, int* __restrict__ list,
                            int* __restrict__ eidx, int* __restrict__ epos,
                            float* __restrict__ wgt)
{
    int warp = threadIdx.x >> 5;
    int lane = threadIdx.x & 31;
    int t = blockIdx.x*4 + warp;
    float acc[Ec];
    #pragma unroll
    for (int e = 0; e < Ec; e++) acc[e] = 0.f;
    const float* xr = xn2 + (size_t)t*Dc;
    for (int k = lane; k < Dc; k += 32){
        float xv = xr[k];
        #pragma unroll
        for (int e = 0; e < Ec; e++) acc[e] += xv * gw[k*Ec + e];
    }
    #pragma unroll
    for (int e = 0; e < Ec; e++){
        #pragma unroll
        for (int o = 16; o; o >>= 1) acc[e] += __shfl_xor_sync(0xffffffffu, acc[e], o);
    }
    if (lane == 0){
        float mx = acc[0];
        #pragma unroll
        for (int e = 1; e < Ec; e++) mx = fmaxf(mx, acc[e]);
        float p[Ec];
        #pragma unroll
        for (int e = 0; e < Ec; e++) p[e] = expf(acc[e] - mx);
        int i0 = 0;
        #pragma unroll
        for (int e = 1; e < Ec; e++) if (p[e] > p[i0]) i0 = e;
        int i1 = (i0 == 0) ? 1 : 0;
        #pragma unroll
        for (int e = 0; e < Ec; e++) if (e != i0 && p[e] > p[i1]) i1 = e;
        float tot = p[i0] + p[i1];
        float w0 = p[i0]/tot, w1 = p[i1]/tot;
        int pos0 = atomicAdd(&cnt[i0], 1);
        int pos1 = atomicAdd(&cnt[i1], 1);
        list[i0*Tc + pos0] = t;
        list[i1*Tc + pos1] = t;
        eidx[2*t]   = i0; epos[2*t]   = pos0; wgt[2*t]   = w0;
        eidx[2*t+1] = i1; epos[2*t+1] = pos1; wgt[2*t+1] = w1;
    }
}

__global__ void prefix_kernel(const int* __restrict__ cnt, int* __restrict__ base){
    if (threadIdx.x == 0){
        int a = 0;
        #pragma unroll
        for (int e = 0; e < Ec; e++){ base[e] = a; a += cnt[e]; }
        base[Ec] = 2*Tc;   // shared expert rows
    }
}

// ---------------- final combine ----------------
__global__ void combine_kernel(const float* __restrict__ x2,
                               const float* __restrict__ eo, const int* __restrict__ eidx,
                               const int* __restrict__ epos, const int* __restrict__ bases,
                               const float* __restrict__ wgt, float* __restrict__ out)
{
    int t = blockIdx.x;
    int g0 = bases[eidx[2*t]]   + epos[2*t];
    int g1 = bases[eidx[2*t+1]] + epos[2*t+1];
    float w0 = wgt[2*t], w1 = wgt[2*t+1];
    int d = threadIdx.x*4;
    size_t o = (size_t)t*Dc + d;
    float4 a  = *(const float4*)&x2[o];
    float4 b  = *(const float4*)&eo[(size_t)(2*Tc + t)*Dc + d];   // shared expert
    float4 c0 = *(const float4*)&eo[(size_t)g0*Dc + d];
    float4 c1 = *(const float4*)&eo[(size_t)g1*Dc + d];
    float4 r;
    r.x = a.x + b.x + w0*c0.x + w1*c1.x;
    r.y = a.y + b.y + w0*c0.y + w1*c1.y;
    r.z = a.z + b.z + w0*c0.z + w1*c1.z;
    r.w = a.w + b.w + w0*c0.w + w1*c1.w;
    *(float4*)&out[o] = r;
}

// ---------------- launch ----------------
extern "C" void kernel_launch(void* const* d_in, const int* in_sizes, int n_in,
                              void* d_out, int out_size)
{
    const float* x   = (const float*)d_in[0];
    const float* qw  = (const float*)d_in[1];
    const float* kvw = (const float*)d_in[2];
    const float* ow  = (const float*)d_in[3];
    const float* gw  = (const float*)d_in[4];
    const float* w1  = (const float*)d_in[5];
    const float* w2  = (const float*)d_in[6];
    const float* w3  = (const float*)d_in[7];
    const float* sw1 = (const float*)d_in[8];
    const float* sw2 = (const float*)d_in[9];
    const float* sw3 = (const float*)d_in[10];
    float* out = (float*)d_out;

    float *x2,*xn2,*eo,*wgt;
    __half *xn,*qkv,*ao,*xn2h,*hbuf;
    __half *qkvT,*owT,*w1T,*w3T,*w2T;
    int *cnt,*base,*list,*eidx,*epos;
    cudaGetSymbolAddress((void**)&xn,   g_xn);
    cudaGetSymbolAddress((void**)&qkv,  g_qkv);
    cudaGetSymbolAddress((void**)&ao,   g_ao);
    cudaGetSymbolAddress((void**)&x2,   g_x2);
    cudaGetSymbolAddress((void**)&xn2,  g_xn2);
    cudaGetSymbolAddress((void**)&xn2h, g_xn2h);
    cudaGetSymbolAddress((void**)&hbuf, g_hbuf);
    cudaGetSymbolAddress((void**)&eo,   g_eo);
    cudaGetSymbolAddress((void**)&wgt,  g_wgt);
    cudaGetSymbolAddress((void**)&qkvT, g_qkvT);
    cudaGetSymbolAddress((void**)&owT,  g_owT);
    cudaGetSymbolAddress((void**)&w1T,  g_w1T);
    cudaGetSymbolAddress((void**)&w3T,  g_w3T);
    cudaGetSymbolAddress((void**)&w2T,  g_w2T);
    cudaGetSymbolAddress((void**)&cnt,  g_cnt);
    cudaGetSymbolAddress((void**)&base, g_base);
    cudaGetSymbolAddress((void**)&list, g_list);
    cudaGetSymbolAddress((void**)&eidx, g_eidx);
    cudaGetSymbolAddress((void**)&epos, g_epos);

    cudaFuncSetAttribute(gemm_f16, cudaFuncAttributeMaxDynamicSharedMemorySize, SM_P);
    cudaFuncSetAttribute(gemm_dual_f16, cudaFuncAttributeMaxDynamicSharedMemorySize, SM_D);

    // merged transposes; shared expert -> slot 8 of expert arrays
    TranspArgs ta;
    const float* srcs[9] = {qw, kvw, ow, w1, w3, w2, sw1, sw3, sw2};
    __half* dsts[9] = {qkvT, qkvT + (size_t)Dc*Dc, owT,
                       w1T, w3T, w2T,
                       w1T + (size_t)Ec*FFc*Dc, w3T + (size_t)Ec*FFc*Dc,
                       w2T + (size_t)Ec*Dc*FFc};
    int Ks[9] = {Dc, Dc, Dc, Dc, Dc, FFc, Dc, Dc, FFc};
    int Ns[9] = {Dc, NKVc, Dc, FFc, FFc, Dc, FFc, FFc, Dc};
    int Bs_[9] = {1, 1, 1, Ec, Ec, Ec, 1, 1, 1};
    int cum = 0;
    for (int i = 0; i < 9; i++){
        ta.src[i] = srcs[i]; ta.dst[i] = dsts[i];
        ta.K[i] = Ks[i]; ta.N[i] = Ns[i];
        ta.cum[i] = cum;
        cum += (Ks[i]/32)*(Ns[i]/32)*Bs_[i];
    }
    ta.cum[9] = cum;
    transp_all<<<cum, dim3(32,8)>>>(ta);

    rms_kernel<<<Tc, 256>>>(x, xn, nullptr);
    gemm_f16<<<dim3(QKVN/64, Tc/128, 1), 256, SM_P>>>(xn, qkvT, nullptr, nullptr, qkv,
                                                      QKVN, Dc, nullptr, nullptr, nullptr, 0);
    attn_kernel<<<Tc, 288>>>(qkv, ao);
    gemm_f16<<<dim3(Dc/64, Tc/128, 1), 256, SM_P>>>(ao, owT, x, x2, nullptr, Dc, Dc,
                                                    nullptr, nullptr, nullptr, 0);
    rms_kernel<<<Tc, 256>>>(x2, xn2h, xn2);
    init_cnt_kernel<<<1, 32>>>(cnt);
    idlist_kernel<<<Tc/256, 256>>>(list);
    gate_kernel<<<Tc/4, 128>>>(xn2, gw, cnt, list, eidx, epos, wgt);
    prefix_kernel<<<1, 32>>>(cnt, base);
    // 9-expert up-proj (routed experts 0-7 gathered; expert 8 = shared, identity)
    gemm_dual_f16<<<dim3(FFc/64, Tc/128, NE), 256, SM_D>>>(xn2h, w1T, w3T, hbuf, FFc, Dc,
                                                           list, cnt, base, (long)FFc*Dc);
    // 9-expert down-proj
    gemm_f16<<<dim3(Dc/64, Tc/128, NE), 256, SM_P>>>(hbuf, w2T, nullptr, eo, nullptr, Dc, FFc,
                                                     nullptr, cnt, base, (long)Dc*FFc);
    combine_kernel<<<Tc, 144>>>(x2, eo, eidx, epos, base, wgt, out);
}

// round 17
// speedup vs baseline: 1.0924x; 1.0466x over previous
#include <cuda_runtime.h>
#include <cuda_fp16.h>
#include <math.h>
#include <stdint.h>

#define Bc 4
#define Sc 2048
#define Dc 576
#define Hc 9
#define HDc 64
#define FFc 1536
#define Ec 8
#define NE (Ec+1)
#define Tc (Bc*Sc)
#define NKVc (Hc*2*HDc)
#define QKVN (Dc + NKVc)   // 1728

// ---------------- scratch ----------------
static __device__ __align__(16) __half g_xn  [Tc*Dc];
static __device__ __align__(16) __half g_qkv [Tc*QKVN];
static __device__ __align__(16) __half g_ao  [Tc*Dc];
static __device__ __align__(16) float  g_x2  [Tc*Dc];
static __device__ __align__(16) __half g_xn2h[Tc*Dc];
static __device__ __align__(16) __half g_hbuf[3*Tc*FFc];
static __device__ __align__(16) float  g_eo  [3*Tc*Dc];
// fp16 transposed weights [N][K]; expert slot 8 = shared expert
static __device__ __align__(16) __half g_qkvT[QKVN*Dc];
static __device__ __align__(16) __half g_owT [Dc*Dc];
static __device__ __align__(16) __half g_w1T [NE*FFc*Dc];
static __device__ __align__(16) __half g_w3T [NE*FFc*Dc];
static __device__ __align__(16) __half g_w2T [NE*Dc*FFc];
static __device__ int   g_cnt [NE];
static __device__ int   g_base[NE];
static __device__ int   g_list[NE*Tc];
static __device__ int   g_eidx[2*Tc];
static __device__ int   g_epos[2*Tc];
static __device__ float g_wgt [2*Tc];

__device__ __forceinline__ float geluf(float x){
    return 0.5f*x*(1.0f + erff(x*0.70710678118654752f));
}
__device__ __forceinline__ uint32_t smem_u32(const void* p){
    uint32_t a;
    asm("{ .reg .u64 t; cvta.to.shared.u64 t, %1; cvt.u32.u64 %0, t; }" : "=r"(a) : "l"(p));
    return a;
}
__device__ __forceinline__ void mma_f16(float* c,
    uint32_t a0,uint32_t a1,uint32_t a2,uint32_t a3, uint32_t b0,uint32_t b1){
    asm("mma.sync.aligned.m16n8k16.row.col.f32.f16.f16.f32 "
        "{%0,%1,%2,%3},{%4,%5,%6,%7},{%8,%9},{%0,%1,%2,%3};"
        : "+f"(c[0]),"+f"(c[1]),"+f"(c[2]),"+f"(c[3])
        : "r"(a0),"r"(a1),"r"(a2),"r"(a3),"r"(b0),"r"(b1));
}
__device__ __forceinline__ void ldsm4(uint32_t* r, uint32_t a){
    asm volatile("ldmatrix.sync.aligned.m8n8.x4.shared.b16 {%0,%1,%2,%3}, [%4];"
        : "=r"(r[0]),"=r"(r[1]),"=r"(r[2]),"=r"(r[3]) : "r"(a));
}
__device__ __forceinline__ void cpa16(uint32_t dst, const void* src, bool pred){
    asm volatile("cp.async.cg.shared.global [%0], [%1], 16, %2;"
        :: "r"(dst), "l"(src), "r"(pred ? 16 : 0));
}
#define CP_COMMIT() asm volatile("cp.async.commit_group;" ::: "memory")
#define CP_WAIT1()  asm volatile("cp.async.wait_group 1;" ::: "memory")
#define CP_WAIT2()  asm volatile("cp.async.wait_group 2;" ::: "memory")
#define CP_WAIT0()  asm volatile("cp.async.wait_group 0;" ::: "memory")

#define PSTG (128*80 + 64*80)
#define DSTG (128*80 + 2*64*80)
#define SM_P (3*PSTG)      // 46080, 3 CTAs/SM
#define SM_D (4*DSTG)      // 81920, 2 CTAs/SM

// ---------------- merged weight transpose: fp32[K][N] -> fp16[N][K] ----------------
struct TranspArgs {
    const float* src[9];
    __half*      dst[9];
    int K[9], N[9];
    int cum[10];
};
__global__ void transp_all(TranspArgs ta){
    __shared__ float tile[32][33];
    int bid = blockIdx.x;
    int e = 0;
    #pragma unroll
    for (int i = 0; i < 9; i++) if (bid >= ta.cum[i+1]) e = i+1;
    int local = bid - ta.cum[e];
    int K = ta.K[e], N = ta.N[e];
    int tilesX = N >> 5, tilesY = K >> 5;
    int perB = tilesX * tilesY;
    int z = local / perB, r = local % perB;
    int n0 = (r % tilesX) << 5, k0 = (r / tilesX) << 5;
    const float* src = ta.src[e] + (size_t)z*K*N;
    __half*      dst = ta.dst[e] + (size_t)z*K*N;
    for (int i = threadIdx.y; i < 32; i += 8)
        tile[i][threadIdx.x] = src[(size_t)(k0+i)*N + n0 + threadIdx.x];
    __syncthreads();
    for (int i = threadIdx.y; i < 32; i += 8)
        dst[(size_t)(n0+i)*K + k0 + threadIdx.x] = __float2half(tile[threadIdx.x][i]);
}

// ---------------- RMSNorm (fp16 out) ----------------
__global__ void rms_kernel(const float* __restrict__ x, __half* __restrict__ yh){
    int t = blockIdx.x;
    const float* xr = x + (size_t)t*Dc;
    float s = 0.f;
    for (int d = threadIdx.x; d < Dc; d += 256){ float v = xr[d]; s += v*v; }
    #pragma unroll
    for (int o = 16; o; o >>= 1) s += __shfl_xor_sync(0xffffffffu, s, o);
    __shared__ float red[9];
    if ((threadIdx.x & 31) == 0) red[threadIdx.x >> 5] = s;
    __syncthreads();
    if (threadIdx.x == 0){
        float tot = 0.f;
        #pragma unroll
        for (int i = 0; i < 8; i++) tot += red[i];
        red[8] = 1.0f / sqrtf(tot*(1.0f/(float)Dc) + 1e-6f);
    }
    __syncthreads();
    float inv = red[8];
    for (int d = threadIdx.x; d < Dc; d += 256)
        yh[(size_t)t*Dc + d] = __float2half(xr[d]*inv);
}

// ---------------- RMSNorm + gate (top-2) fused ----------------
__global__ void rms_gate_kernel(const float* __restrict__ x, __half* __restrict__ yh,
                                const float* __restrict__ gw,
                                int* __restrict__ cnt, int* __restrict__ list,
                                int* __restrict__ eidx, int* __restrict__ epos,
                                float* __restrict__ wgt)
{
    int t = blockIdx.x;
    const float* xr = x + (size_t)t*Dc;
    float s = 0.f;
    for (int d = threadIdx.x; d < Dc; d += 256){ float v = xr[d]; s += v*v; }
    #pragma unroll
    for (int o = 16; o; o >>= 1) s += __shfl_xor_sync(0xffffffffu, s, o);
    __shared__ float red[8];
    __shared__ float gred[8][8];
    __shared__ float inv_s;
    if ((threadIdx.x & 31) == 0) red[threadIdx.x >> 5] = s;
    __syncthreads();
    if (threadIdx.x == 0){
        float tot = 0.f;
        #pragma unroll
        for (int i = 0; i < 8; i++) tot += red[i];
        inv_s = 1.0f / sqrtf(tot*(1.0f/(float)Dc) + 1e-6f);
    }
    __syncthreads();
    float inv = inv_s;
    float acc[Ec];
    #pragma unroll
    for (int e = 0; e < Ec; e++) acc[e] = 0.f;
    for (int d = threadIdx.x; d < Dc; d += 256){
        float v = xr[d]*inv;
        yh[(size_t)t*Dc + d] = __float2half(v);
        const float4* gp = (const float4*)&gw[d*Ec];
        float4 g0 = gp[0], g1 = gp[1];
        acc[0] += v*g0.x; acc[1] += v*g0.y; acc[2] += v*g0.z; acc[3] += v*g0.w;
        acc[4] += v*g1.x; acc[5] += v*g1.y; acc[6] += v*g1.z; acc[7] += v*g1.w;
    }
    #pragma unroll
    for (int e = 0; e < Ec; e++){
        #pragma unroll
        for (int o = 16; o; o >>= 1) acc[e] += __shfl_xor_sync(0xffffffffu, acc[e], o);
    }
    if ((threadIdx.x & 31) == 0){
        int w = threadIdx.x >> 5;
        #pragma unroll
        for (int e = 0; e < Ec; e++) gred[w][e] = acc[e];
    }
    __syncthreads();
    if (threadIdx.x == 0){
        float lg[Ec];
        #pragma unroll
        for (int e = 0; e < Ec; e++){
            float a = 0.f;
            #pragma unroll
            for (int w = 0; w < 8; w++) a += gred[w][e];
            lg[e] = a;
        }
        float mx = lg[0];
        #pragma unroll
        for (int e = 1; e < Ec; e++) mx = fmaxf(mx, lg[e]);
        float p[Ec];
        #pragma unroll
        for (int e = 0; e < Ec; e++) p[e] = expf(lg[e] - mx);
        int i0 = 0;
        #pragma unroll
        for (int e = 1; e < Ec; e++) if (p[e] > p[i0]) i0 = e;
        int i1 = (i0 == 0) ? 1 : 0;
        #pragma unroll
        for (int e = 0; e < Ec; e++) if (e != i0 && p[e] > p[i1]) i1 = e;
        float tot = p[i0] + p[i1];
        float w0 = p[i0]/tot, w1 = p[i1]/tot;
        int pos0 = atomicAdd(&cnt[i0], 1);
        int pos1 = atomicAdd(&cnt[i1], 1);
        list[i0*Tc + pos0] = t;
        list[i1*Tc + pos1] = t;
        eidx[2*t]   = i0; epos[2*t]   = pos0; wgt[2*t]   = w0;
        eidx[2*t+1] = i1; epos[2*t+1] = pos1; wgt[2*t+1] = w1;
    }
}

// ---------------- per-token 9x9 head attention (RoPE fused), fp16 in/out ----------------
__global__ __launch_bounds__(288) void attn_kernel(const __half* __restrict__ qkv,
                                                   __half* __restrict__ ao)
{
    int t = blockIdx.x;
    int h = threadIdx.x >> 5;
    int lane = threadIdx.x & 31;
    int s = t & (Sc-1);
    int b = t >> 11;
    float theta = exp2f(-0.41524101186092029f*(float)lane);
    float fr = (float)s * theta;
    float sn, cs; sincosf(fr, &sn, &cs);
    const __half* row = qkv + (size_t)t*QKVN;
    float2 qv = __half22float2(((const __half2*)(row + h*HDc))[lane]);
    float q0 = qv.x*cs - qv.y*sn;
    float q1 = qv.x*sn + qv.y*cs;
    const __half* kvb = row + Dc;
    float sc[Hc];
    #pragma unroll
    for (int t9 = 0; t9 < Hc; t9++){
        float2 k2 = __half22float2(((const __half2*)(kvb + t9*2*HDc))[lane]);
        float p = q0*k2.x + q1*k2.y;
        #pragma unroll
        for (int o = 16; o; o >>= 1) p += __shfl_xor_sync(0xffffffffu, p, o);
        sc[t9] = p*0.125f;
    }
    float mx = sc[0];
    #pragma unroll
    for (int t9 = 1; t9 < Hc; t9++) mx = fmaxf(mx, sc[t9]);
    float pr[Hc]; float sum = 0.f;
    #pragma unroll
    for (int t9 = 0; t9 < Hc; t9++){ pr[t9] = expf(sc[t9]-mx); sum += pr[t9]; }
    float inv = 1.0f/sum;
    float o0 = 0.f, o1 = 0.f;
    #pragma unroll
    for (int t9 = 0; t9 < Hc; t9++){
        float2 v2 = __half22float2(((const __half2*)(kvb + t9*2*HDc + HDc))[lane]);
        o0 += pr[t9]*v2.x;
        o1 += pr[t9]*v2.y;
    }
    __half2* op = (__half2*)(ao + ((((size_t)(b*Hc + h))*Sc + s)*HDc));
    op[lane] = __floats2half2_rn(o0*inv, o1*inv);
}

// ================= fp16 GEMM: ldmatrix + cp.async 3-stage, 3 CTAs/SM =================
__global__ __launch_bounds__(256,3) void gemm_f16(const __half* __restrict__ A,
                                                  const __half* __restrict__ BT,
                                                  const float* __restrict__ Res,
                                                  float* __restrict__ C,
                                                  __half* __restrict__ Ch,
                                                  int N, int Kd,
                                                  const int* __restrict__ gather,
                                                  const int* __restrict__ cnts,
                                                  const int* __restrict__ bases,
                                                  long bstride)
{
    extern __shared__ char sm[];
    uint32_t sb = smem_u32(sm);

    int Mloc = Tc; long base = 0; const int* gl = nullptr;
    if (cnts){
        int e = blockIdx.z;
        Mloc = cnts[e]; base = bases[e];
        BT += (size_t)e*bstride;
        if (gather) gl = gather + e*Tc;
    }
    int row0 = blockIdx.y*128;
    if (row0 >= Mloc) return;
    int n0 = blockIdx.x*64;

    const int tid = threadIdx.x, wid = tid>>5, lane = tid&31;
    const int wm = wid & 3, wn = wid >> 2;
    const int g = lane >> 2, tg = lane & 3;

    const int lrow = tid >> 2;
    const int lh8  = (tid & 3) * 8;
    int r0l = row0 + lrow, r1l = row0 + lrow + 64;
    bool v0 = r0l < Mloc, v1 = r1l < Mloc;
    long tok0 = gl ? (v0 ? (long)gl[r0l] : 0) : (base + (v0 ? r0l : 0));
    long tok1 = gl ? (v1 ? (long)gl[r1l] : 0) : (base + (v1 ? r1l : 0));
    const __half* Ap0 = A + (size_t)tok0*Kd + lh8;
    const __half* Ap1 = A + (size_t)tok1*Kd + lh8;
    const __half* Bp  = BT + (size_t)(n0 + lrow)*Kd + lh8;

    uint32_t aDst0 = sb + lrow*80 + lh8*2;
    uint32_t aDst1 = sb + (lrow+64)*80 + lh8*2;
    uint32_t bDst  = sb + 128*80 + lrow*80 + lh8*2;

    const int ra = lane & 15, ca = (lane >> 4) << 3;
    const int rb = (lane & 7) + ((lane >> 4) << 3), cb = lane & 8;
    uint32_t aAdr[2], bAdr[2];
    #pragma unroll
    for (int mt=0; mt<2; mt++) aAdr[mt] = sb + (wm*32 + mt*16 + ra)*80 + ca*2;
    #pragma unroll
    for (int np=0; np<2; np++) bAdr[np] = sb + 128*80 + (wn*32 + np*16 + rb)*80 + cb*2;

    float acc[2][4][4];
    #pragma unroll
    for (int mt=0; mt<2; mt++)
        #pragma unroll
        for (int nt=0; nt<4; nt++)
            #pragma unroll
            for (int i=0;i<4;i++) acc[mt][nt][i]=0.f;

    int nc = Kd >> 5;
    #pragma unroll 1
    for (int p = 0; p < 2; p++){
        uint32_t o = p*PSTG; int k0 = p<<5;
        cpa16(aDst0+o, Ap0 + k0, v0);
        cpa16(aDst1+o, Ap1 + k0, v1);
        cpa16(bDst +o, Bp  + k0, true);
        CP_COMMIT();
    }

    int sc_ = 0, sp_ = 2;
    for (int c = 0; c < nc; c++){
        uint32_t so = (uint32_t)sc_*PSTG;
        CP_WAIT1();
        __syncthreads();
        if (c + 2 < nc){
            uint32_t o = (uint32_t)sp_*PSTG; int k0 = (c+2)<<5;
            cpa16(aDst0+o, Ap0 + k0, v0);
            cpa16(aDst1+o, Ap1 + k0, v1);
            cpa16(bDst +o, Bp  + k0, true);
        }
        CP_COMMIT();
        #pragma unroll
        for (int h = 0; h < 2; h++){
            uint32_t af[2][4], bf[2][4];
            #pragma unroll
            for (int mt=0; mt<2; mt++) ldsm4(af[mt], aAdr[mt] + so + h*32);
            #pragma unroll
            for (int np=0; np<2; np++) ldsm4(bf[np], bAdr[np] + so + h*32);
            #pragma unroll
            for (int np=0; np<2; np++)
                #pragma unroll
                for (int j=0; j<2; j++){
                    int nt = np*2 + j;
                    #pragma unroll
                    for (int mt=0; mt<2; mt++)
                        mma_f16(acc[mt][nt], af[mt][0],af[mt][1],af[mt][2],af[mt][3],
                                bf[np][j*2], bf[np][j*2+1]);
                }
        }
        sc_ = (sc_+1 == 3) ? 0 : sc_+1;
        sp_ = (sp_+1 == 3) ? 0 : sp_+1;
    }
    CP_WAIT0();

    #pragma unroll
    for (int mt=0; mt<2; mt++){
        #pragma unroll
        for (int nt=0; nt<4; nt++){
            int r = row0 + wm*32 + mt*16 + g;
            int c = n0 + wn*32 + nt*8 + tg*2;
            if (Ch){
                if (r < Mloc)
                    *(__half2*)&Ch[(size_t)(base+r)*N + c] =
                        __floats2half2_rn(acc[mt][nt][0], acc[mt][nt][1]);
                if (r + 8 < Mloc)
                    *(__half2*)&Ch[(size_t)(base+r+8)*N + c] =
                        __floats2half2_rn(acc[mt][nt][2], acc[mt][nt][3]);
            } else {
                if (r < Mloc){
                    float2 v = make_float2(acc[mt][nt][0], acc[mt][nt][1]);
                    if (Res){
                        const float2 rv = *(const float2*)&Res[(size_t)(base+r)*N + c];
                        v.x += rv.x; v.y += rv.y;
                    }
                    *(float2*)&C[(size_t)(base+r)*N + c] = v;
                }
                if (r + 8 < Mloc){
                    float2 v = make_float2(acc[mt][nt][2], acc[mt][nt][3]);
                    if (Res){
                        const float2 rv = *(const float2*)&Res[(size_t)(base+r+8)*N + c];
                        v.x += rv.x; v.y += rv.y;
                    }
                    *(float2*)&C[(size_t)(base+r+8)*N + c] = v;
                }
            }
        }
    }
}

// ----- dual: C(fp16) = gelu(A@B1T^T)*(A@B3T^T), cp.async 4-stage (R13 config) -----
__global__ __launch_bounds__(256,2) void gemm_dual_f16(const __half* __restrict__ A,
                                                       const __half* __restrict__ B1T,
                                                       const __half* __restrict__ B3T,
                                                       __half* __restrict__ C,
                                                       int N, int Kd,
                                                       const int* __restrict__ gather,
                                                       const int* __restrict__ cnts,
                                                       const int* __restrict__ bases,
                                                       long bstride)
{
    extern __shared__ char sm[];
    uint32_t sb = smem_u32(sm);

    int Mloc = Tc; long base = 0; const int* gl = nullptr;
    if (cnts){
        int e = blockIdx.z;
        Mloc = cnts[e]; base = bases[e];
        B1T += (size_t)e*bstride;
        B3T += (size_t)e*bstride;
        if (gather) gl = gather + e*Tc;
    }
    int row0 = blockIdx.y*128;
    if (row0 >= Mloc) return;
    int n0 = blockIdx.x*64;

    const int tid = threadIdx.x, wid = tid>>5, lane = tid&31;
    const int wm = wid & 3, wn = wid >> 2;
    const int g = lane >> 2, tg = lane & 3;

    const int lrow = tid >> 2;
    const int lh8  = (tid & 3) * 8;
    int r0l = row0 + lrow, r1l = row0 + lrow + 64;
    bool v0 = r0l < Mloc, v1 = r1l < Mloc;
    long tok0 = gl ? (v0 ? (long)gl[r0l] : 0) : (base + (v0 ? r0l : 0));
    long tok1 = gl ? (v1 ? (long)gl[r1l] : 0) : (base + (v1 ? r1l : 0));
    const __half* Ap0 = A + (size_t)tok0*Kd + lh8;
    const __half* Ap1 = A + (size_t)tok1*Kd + lh8;
    const __half* B1p = B1T + (size_t)(n0 + lrow)*Kd + lh8;
    const __half* B3p = B3T + (size_t)(n0 + lrow)*Kd + lh8;

    uint32_t aDst0 = sb + lrow*80 + lh8*2;
    uint32_t aDst1 = sb + (lrow+64)*80 + lh8*2;
    uint32_t b1Dst = sb + 128*80 + lrow*80 + lh8*2;
    uint32_t b3Dst = sb + 128*80 + 64*80 + lrow*80 + lh8*2;

    const int ra = lane & 15, ca = (lane >> 4) << 3;
    const int rb = (lane & 7) + ((lane >> 4) << 3), cb = lane & 8;
    uint32_t aAdr[2], b1Adr[2], b3Adr[2];
    #pragma unroll
    for (int mt=0; mt<2; mt++) aAdr[mt] = sb + (wm*32 + mt*16 + ra)*80 + ca*2;
    #pragma unroll
    for (int np=0; np<2; np++){
        b1Adr[np] = sb + 128*80 + (wn*32 + np*16 + rb)*80 + cb*2;
        b3Adr[np] = sb + 128*80 + 64*80 + (wn*32 + np*16 + rb)*80 + cb*2;
    }

    float acc1[2][4][4], acc3[2][4][4];
    #pragma unroll
    for (int mt=0; mt<2; mt++)
        #pragma unroll
        for (int nt=0; nt<4; nt++)
            #pragma unroll
            for (int i=0;i<4;i++){ acc1[mt][nt][i]=0.f; acc3[mt][nt][i]=0.f; }

    int nc = Kd >> 5;
    #pragma unroll 1
    for (int p = 0; p < 3; p++){
        uint32_t o = p*DSTG; int k0 = p<<5;
        cpa16(aDst0+o, Ap0 + k0, v0);
        cpa16(aDst1+o, Ap1 + k0, v1);
        cpa16(b1Dst+o, B1p + k0, true);
        cpa16(b3Dst+o, B3p + k0, true);
        CP_COMMIT();
    }

    for (int c = 0; c < nc; c++){
        uint32_t so = (uint32_t)(c & 3)*DSTG;
        CP_WAIT2();
        __syncthreads();
        if (c + 3 < nc){
            uint32_t o = (uint32_t)((c+3) & 3)*DSTG; int k0 = (c+3)<<5;
            cpa16(aDst0+o, Ap0 + k0, v0);
            cpa16(aDst1+o, Ap1 + k0, v1);
            cpa16(b1Dst+o, B1p + k0, true);
            cpa16(b3Dst+o, B3p + k0, true);
        }
        CP_COMMIT();
        #pragma unroll
        for (int h = 0; h < 2; h++){
            uint32_t af[2][4], bf1[2][4], bf3[2][4];
            #pragma unroll
            for (int mt=0; mt<2; mt++) ldsm4(af[mt], aAdr[mt] + so + h*32);
            #pragma unroll
            for (int np=0; np<2; np++){
                ldsm4(bf1[np], b1Adr[np] + so + h*32);
                ldsm4(bf3[np], b3Adr[np] + so + h*32);
            }
            #pragma unroll
            for (int np=0; np<2; np++)
                #pragma unroll
                for (int j=0; j<2; j++){
                    int nt = np*2 + j;
                    #pragma unroll
                    for (int mt=0; mt<2; mt++){
                        mma_f16(acc1[mt][nt], af[mt][0],af[mt][1],af[mt][2],af[mt][3],
                                bf1[np][j*2], bf1[np][j*2+1]);
                        mma_f16(acc3[mt][nt], af[mt][0],af[mt][1],af[mt][2],af[mt][3],
                                bf3[np][j*2], bf3[np][j*2+1]);
                    }
                }
        }
    }
    CP_WAIT0();

    #pragma unroll
    for (int mt=0; mt<2; mt++){
        #pragma unroll
        for (int nt=0; nt<4; nt++){
            int r = row0 + wm*32 + mt*16 + g;
            int c = n0 + wn*32 + nt*8 + tg*2;
            if (r < Mloc){
                *(__half2*)&C[(size_t)(base+r)*N + c] = __floats2half2_rn(
                    geluf(acc1[mt][nt][0])*acc3[mt][nt][0],
                    geluf(acc1[mt][nt][1])*acc3[mt][nt][1]);
            }
            if (r + 8 < Mloc){
                *(__half2*)&C[(size_t)(base+r+8)*N + c] = __floats2half2_rn(
                    geluf(acc1[mt][nt][2])*acc3[mt][nt][2],
                    geluf(acc1[mt][nt][3])*acc3[mt][nt][3]);
            }
        }
    }
}

// ---------------- misc ----------------
__global__ void init_cnt_kernel(int* cnt){
    if (threadIdx.x < Ec) cnt[threadIdx.x] = 0;
    if (threadIdx.x == Ec) cnt[Ec] = Tc;
}
__global__ void idlist_kernel(int* __restrict__ list){
    int i = blockIdx.x*256 + threadIdx.x;
    list[Ec*Tc + i] = i;
}
__global__ void prefix_kernel(const int* __restrict__ cnt, int* __restrict__ base){
    if (threadIdx.x == 0){
        int a = 0;
        #pragma unroll
        for (int e = 0; e < Ec; e++){ base[e] = a; a += cnt[e]; }
        base[Ec] = 2*Tc;
    }
}

// ---------------- final combine ----------------
__global__ void combine_kernel(const float* __restrict__ x2,
                               const float* __restrict__ eo, const int* __restrict__ eidx,
                               const int* __restrict__ epos, const int* __restrict__ bases,
                               const float* __restrict__ wgt, float* __restrict__ out)
{
    int t = blockIdx.x;
    int g0 = bases[eidx[2*t]]   + epos[2*t];
    int g1 = bases[eidx[2*t+1]] + epos[2*t+1];
    float w0 = wgt[2*t], w1 = wgt[2*t+1];
    int d = threadIdx.x*4;
    size_t o = (size_t)t*Dc + d;
    float4 a  = *(const float4*)&x2[o];
    float4 b  = *(const float4*)&eo[(size_t)(2*Tc + t)*Dc + d];
    float4 c0 = *(const float4*)&eo[(size_t)g0*Dc + d];
    float4 c1 = *(const float4*)&eo[(size_t)g1*Dc + d];
    float4 r;
    r.x = a.x + b.x + w0*c0.x + w1*c1.x;
    r.y = a.y + b.y + w0*c0.y + w1*c1.y;
    r.z = a.z + b.z + w0*c0.z + w1*c1.z;
    r.w = a.w + b.w + w0*c0.w + w1*c1.w;
    *(float4*)&out[o] = r;
}

// ---------------- launch ----------------
extern "C" void kernel_launch(void* const* d_in, const int* in_sizes, int n_in,
                              void* d_out, int out_size)
{
    const float* x   = (const float*)d_in[0];
    const float* qw  = (const float*)d_in[1];
    const float* kvw = (const float*)d_in[2];
    const float* ow  = (const float*)d_in[3];
    const float* gw  = (const float*)d_in[4];
    const float* w1  = (const float*)d_in[5];
    const float* w2  = (const float*)d_in[6];
    const float* w3  = (const float*)d_in[7];
    const float* sw1 = (const float*)d_in[8];
    const float* sw2 = (const float*)d_in[9];
    const float* sw3 = (const float*)d_in[10];
    float* out = (float*)d_out;

    float *x2,*eo,*wgt;
    __half *xn,*qkv,*ao,*xn2h,*hbuf;
    __half *qkvT,*owT,*w1T,*w3T,*w2T;
    int *cnt,*base,*list,*eidx,*epos;
    cudaGetSymbolAddress((void**)&xn,   g_xn);
    cudaGetSymbolAddress((void**)&qkv,  g_qkv);
    cudaGetSymbolAddress((void**)&ao,   g_ao);
    cudaGetSymbolAddress((void**)&x2,   g_x2);
    cudaGetSymbolAddress((void**)&xn2h, g_xn2h);
    cudaGetSymbolAddress((void**)&hbuf, g_hbuf);
    cudaGetSymbolAddress((void**)&eo,   g_eo);
    cudaGetSymbolAddress((void**)&wgt,  g_wgt);
    cudaGetSymbolAddress((void**)&qkvT, g_qkvT);
    cudaGetSymbolAddress((void**)&owT,  g_owT);
    cudaGetSymbolAddress((void**)&w1T,  g_w1T);
    cudaGetSymbolAddress((void**)&w3T,  g_w3T);
    cudaGetSymbolAddress((void**)&w2T,  g_w2T);
    cudaGetSymbolAddress((void**)&cnt,  g_cnt);
    cudaGetSymbolAddress((void**)&base, g_base);
    cudaGetSymbolAddress((void**)&list, g_list);
    cudaGetSymbolAddress((void**)&eidx, g_eidx);
    cudaGetSymbolAddress((void**)&epos, g_epos);

    cudaFuncSetAttribute(gemm_f16, cudaFuncAttributeMaxDynamicSharedMemorySize, SM_P);
    cudaFuncSetAttribute(gemm_dual_f16, cudaFuncAttributeMaxDynamicSharedMemorySize, SM_D);

    TranspArgs ta;
    const float* srcs[9] = {qw, kvw, ow, w1, w3, w2, sw1, sw3, sw2};
    __half* dsts[9] = {qkvT, qkvT + (size_t)Dc*Dc, owT,
                       w1T, w3T, w2T,
                       w1T + (size_t)Ec*FFc*Dc, w3T + (size_t)Ec*FFc*Dc,
                       w2T + (size_t)Ec*Dc*FFc};
    int Ks[9] = {Dc, Dc, Dc, Dc, Dc, FFc, Dc, Dc, FFc};
    int Ns[9] = {Dc, NKVc, Dc, FFc, FFc, Dc, FFc, FFc, Dc};
    int Bs_[9] = {1, 1, 1, Ec, Ec, Ec, 1, 1, 1};
    int cum = 0;
    for (int i = 0; i < 9; i++){
        ta.src[i] = srcs[i]; ta.dst[i] = dsts[i];
        ta.K[i] = Ks[i]; ta.N[i] = Ns[i];
        ta.cum[i] = cum;
        cum += (Ks[i]/32)*(Ns[i]/32)*Bs_[i];
    }
    ta.cum[9] = cum;
    transp_all<<<cum, dim3(32,8)>>>(ta);

    rms_kernel<<<Tc, 256>>>(x, xn);
    gemm_f16<<<dim3(QKVN/64, Tc/128, 1), 256, SM_P>>>(xn, qkvT, nullptr, nullptr, qkv,
                                                      QKVN, Dc, nullptr, nullptr, nullptr, 0);
    attn_kernel<<<Tc, 288>>>(qkv, ao);
    gemm_f16<<<dim3(Dc/64, Tc/128, 1), 256, SM_P>>>(ao, owT, x, x2, nullptr, Dc, Dc,
                                                    nullptr, nullptr, nullptr, 0);
    init_cnt_kernel<<<1, 32>>>(cnt);
    idlist_kernel<<<Tc/256, 256>>>(list);
    rms_gate_kernel<<<Tc, 256>>>(x2, xn2h, gw, cnt, list, eidx, epos, wgt);
    prefix_kernel<<<1, 32>>>(cnt, base);
    gemm_dual_f16<<<dim3(FFc/64, Tc/128, NE), 256, SM_D>>>(xn2h, w1T, w3T, hbuf, FFc, Dc,
                                                           list, cnt, base, (long)FFc*Dc);
    gemm_f16<<<dim3(Dc/64, Tc/128, NE), 256, SM_P>>>(hbuf, w2T, nullptr, eo, nullptr, Dc, FFc,
                                                     nullptr, cnt, base, (long)Dc*FFc);
    combine_kernel<<<Tc, 144>>>(x2, eo, eidx, epos, base, wgt, out);
}